// round 11
// baseline (speedup 1.0000x reference)
#include <cuda_runtime.h>
#include <cuda_fp16.h>
#include <cstdint>
#include <math.h>

#define N_SPK 2048
#define M_UTT 16
#define D_DIM 128
#define ROWS  32768

#define BM 64                   // rows per CTA
#define NCTA (ROWS / BM)        // 512
#define NSTAGE 32               // 64-col stages over N_SPK
#define THREADS 128

#define A_U4 (4 * 8 * 32)       // per-CTA packed A uint4 = 1024
#define STG_U4 1024             // 16KB per 64-col stage
#define DYN_SMEM (2 * STG_U4 * 16)   // 32KB: B double buffer (A in regs)

// packed fp16 operands in fragment order (__device__ scratch; no cudaMalloc)
__device__ uint4 gAh[NCTA * A_U4];               // 8MB
__device__ uint4 gBh[NSTAGE * STG_U4];           // 512KB
__device__ float g_partial[NCTA];
__device__ unsigned g_ctr = 0;

// ---------------------------------------------------------------------------
__device__ __forceinline__ void cp_async16(uint32_t dst, const void* src) {
    asm volatile("cp.async.cg.shared.global [%0], [%1], 16;" :: "r"(dst), "l"(src));
}
__device__ __forceinline__ uint32_t smem_u32(const void* p) {
    uint32_t a;
    asm("{ .reg .u64 t; cvta.to.shared.u64 t, %1; cvt.u32.u64 %0, t; }" : "=r"(a) : "l"(p));
    return a;
}
#define CP_COMMIT() asm volatile("cp.async.commit_group;" ::: "memory")
#define CP_WAIT0()  asm volatile("cp.async.wait_group 0;" ::: "memory")

__device__ __forceinline__ uint32_t pack2(float lo, float hi) {
    __half2 h = __floats2half2_rn(lo, hi);
    return *reinterpret_cast<uint32_t*>(&h);
}
__device__ __forceinline__ float ex2(float x) {
    float y;
    asm("ex2.approx.f32 %0, %1;" : "=f"(y) : "f"(x));
    return y;
}
// ---- f16x2 epilogue helpers ----
__device__ __forceinline__ uint32_t cvt2h(float a, float b) {   // pack two f32 -> f16x2
    uint32_t d;
    asm("cvt.rn.f16x2.f32 %0, %1, %2;" : "=r"(d) : "f"(a), "f"(b));
    return d;
}
__device__ __forceinline__ uint32_t hfma2(uint32_t a, uint32_t b, uint32_t c) {
    uint32_t d;
    asm("fma.rn.f16x2 %0, %1, %2, %3;" : "=r"(d) : "r"(a), "r"(b), "r"(c));
    return d;
}
__device__ __forceinline__ uint32_t ex2h2(uint32_t a) {
    uint32_t d;
    asm("ex2.approx.f16x2 %0, %1;" : "=r"(d) : "r"(a));
    return d;
}
__device__ __forceinline__ uint32_t hadd2(uint32_t a, uint32_t b) {
    uint32_t d;
    asm("add.rn.f16x2 %0, %1, %2;" : "=r"(d) : "r"(a), "r"(b));
    return d;
}
__device__ __forceinline__ float hsum2(uint32_t v) {            // f16x2 -> f32 sum
    float lo, hi;
    asm("{ .reg .b16 l, h; mov.b32 {l, h}, %2; cvt.f32.f16 %0, l; cvt.f32.f16 %1, h; }"
        : "=f"(lo), "=f"(hi) : "r"(v));
    return lo + hi;
}

#define MMA(d, a, b0, b1) \
    asm volatile("mma.sync.aligned.m16n8k16.row.col.f32.f16.f16.f32 " \
                 "{%0,%1,%2,%3},{%4,%5,%6,%7},{%8,%9},{%0,%1,%2,%3};" \
                 : "+f"((d)[0]), "+f"((d)[1]), "+f"((d)[2]), "+f"((d)[3]) \
                 : "r"((a).x), "r"((a).y), "r"((a).z), "r"((a).w), "r"(b0), "r"(b1))
#define MMA_INIT(d, a, b0, b1) \
    asm volatile("mma.sync.aligned.m16n8k16.row.col.f32.f16.f16.f32 " \
                 "{%0,%1,%2,%3},{%4,%5,%6,%7},{%8,%9},{%10,%10,%10,%10};" \
                 : "=f"((d)[0]), "=f"((d)[1]), "=f"((d)[2]), "=f"((d)[3]) \
                 : "r"((a).x), "r"((a).y), "r"((a).z), "r"((a).w), "r"(b0), "r"(b1), "f"(0.f))

// ---------------------------------------------------------------------------
// Fused pre-pack: blocks [0,2048) pack A; blocks [2048,2176) pack B.
// A: id = [cta9][mt2][ks3][lane5]
// ---------------------------------------------------------------------------
__global__ __launch_bounds__(256) void pack_ab_kernel(const float* __restrict__ x) {
    if (blockIdx.x < 2048) {
        int id = blockIdx.x * 256 + threadIdx.x;        // 0..524287
        int lane = id & 31, ks = (id >> 5) & 7, mt = (id >> 8) & 3, cta = id >> 10;
        int g = lane >> 2, t = lane & 3;
        int r0 = cta * BM + mt * 16 + g;
        int k0 = ks * 16 + t * 2;
        const float* p0 = x + (size_t)r0 * D_DIM;
        const float* p1 = p0 + 8 * D_DIM;
        float2 alo = *(const float2*)(p0 + k0);
        float2 blo = *(const float2*)(p1 + k0);
        float2 ahi = *(const float2*)(p0 + k0 + 8);
        float2 bhi = *(const float2*)(p1 + k0 + 8);
        uint4 o;
        o.x = pack2(alo.x, alo.y);
        o.y = pack2(blo.x, blo.y);
        o.z = pack2(ahi.x, ahi.y);
        o.w = pack2(bhi.x, bhi.y);
        gAh[id] = o;
    } else {
        int id = (blockIdx.x - 2048) * 256 + threadIdx.x;   // 0..32767
        int lane = id & 31, pp = (id >> 5) & 3, ks = (id >> 7) & 7, t = id >> 10;
        int g = lane >> 2, tt = lane & 3;
        int col0 = t * 64 + pp * 16 + g;
        int k0 = ks * 16 + tt * 2;
        const float* base0 = x + (size_t)col0 * M_UTT * D_DIM;
        const float* base1 = base0 + (size_t)8 * M_UTT * D_DIM;
        float2 s0l = {0.f, 0.f}, s0h = {0.f, 0.f}, s1l = {0.f, 0.f}, s1h = {0.f, 0.f};
#pragma unroll
        for (int m = 0; m < M_UTT; m++) {
            const float* r0 = base0 + m * D_DIM;
            const float* r1 = base1 + m * D_DIM;
            float2 v;
            v = *(const float2*)(r0 + k0);     s0l.x += v.x; s0l.y += v.y;
            v = *(const float2*)(r0 + k0 + 8); s0h.x += v.x; s0h.y += v.y;
            v = *(const float2*)(r1 + k0);     s1l.x += v.x; s1l.y += v.y;
            v = *(const float2*)(r1 + k0 + 8); s1h.x += v.x; s1h.y += v.y;
        }
        const float inv = 1.0f / M_UTT;
        uint4 o;
        o.x = pack2(s0l.x * inv, s0l.y * inv);
        o.y = pack2(s0h.x * inv, s0h.y * inv);
        o.z = pack2(s1l.x * inv, s1l.y * inv);
        o.w = pack2(s1h.x * inv, s1h.y * inv);
        gBh[id] = o;
    }
}

// ---------------------------------------------------------------------------
__device__ __forceinline__ void load_stage(uint32_t ringBase, int t, int tid) {
    const uint4* src = gBh + (size_t)t * STG_U4;
    uint32_t dst = ringBase + (t & 1) * (STG_U4 * 16);
#pragma unroll
    for (int i = 0; i < 8; i++)
        cp_async16(dst + (tid + i * THREADS) * 16, src + tid + i * THREADS);
}

// ---------------------------------------------------------------------------
// Main: fp16 mma.sync GEMM + log2-softmax. BM=64, THREADS=128, 4 CTAs/SM:
// four independent barrier domains per SM self-stagger tensor/MUFU/LDS.
// A in registers; B double-buffered (32KB). f16x2 epilogue on non-diag stages.
// ---------------------------------------------------------------------------
__global__ __launch_bounds__(THREADS, 4) void ge2e_main(const float* __restrict__ wp,
                                                        const float* __restrict__ bp,
                                                        float* __restrict__ out) {
    extern __shared__ uint4 dsm[];
    __shared__ float s_tgt[BM];
    __shared__ float s_red[BM][2];
    __shared__ float s_loss[BM];
    __shared__ bool  s_last;

    const int tid  = threadIdx.x;
    const int wid  = tid >> 5;
    const int lane = tid & 31;
    const int wm = wid >> 1;            // 0..1
    const int wn = wid & 1;             // 0..1
    const int g  = lane >> 2;
    const int t4 = lane & 3;

    const float L2E = 1.44269504088896341f;
    const float w2  = wp[0] * L2E;
    const float b2  = bp[0] * L2E;
    const float wd  = w2 * (16.0f / 15.0f);
    const float bd  = b2 - w2 * (1.0f / 15.0f);
    const uint32_t w2h = pack2(w2, w2);
    const uint32_t b2h = pack2(b2, b2);

    const uint32_t ringB = smem_u32(dsm);
    const int t_diag = blockIdx.x >> 4;     // stage holding this CTA's self cols

    // stage0 B copy first; overlaps the A register loads
    load_stage(ringB, 0, tid);
    CP_COMMIT();

    // A -> registers (64 regs), reused for all 32 stages
    uint4 areg[2][8];
    {
        const uint4* gAs = gAh + (size_t)blockIdx.x * A_U4;
#pragma unroll
        for (int i = 0; i < 2; i++)
#pragma unroll
            for (int s = 0; s < 8; s++)
                areg[i][s] = gAs[((wm * 2 + i) * 8 + s) * 32 + lane];
    }

    float acc[2][4][4];
    float rsum[2][2] = {};
    int lrow[2], sp0[2], sp1[2];
#pragma unroll
    for (int mt = 0; mt < 2; mt++) {
        lrow[mt] = wm * 32 + mt * 16 + g;
        int gr = blockIdx.x * BM + lrow[mt];
        sp0[mt] = gr >> 4;
        sp1[mt] = (gr + 8) >> 4;
    }

    for (int t = 0; t < NSTAGE; t++) {
        CP_WAIT0();
        __syncthreads();
        if (t + 1 < NSTAGE) {
            load_stage(ringB, t + 1, tid);
            CP_COMMIT();
        }

        const uint4* Bst = dsm + (t & 1) * STG_U4;

        // ---- MMA: 8 k-steps, A from registers, 2 LDS per step ----
#pragma unroll
        for (int s = 0; s < 8; s++) {
            uint4 q0 = Bst[(s * 4 + wn * 2 + 0) * 32 + lane];
            uint4 q1 = Bst[(s * 4 + wn * 2 + 1) * 32 + lane];
            if (s == 0) {
                MMA_INIT(acc[0][0], areg[0][0], q0.x, q0.y); MMA_INIT(acc[0][1], areg[0][0], q0.z, q0.w);
                MMA_INIT(acc[1][0], areg[1][0], q0.x, q0.y); MMA_INIT(acc[1][1], areg[1][0], q0.z, q0.w);
                MMA_INIT(acc[0][2], areg[0][0], q1.x, q1.y); MMA_INIT(acc[0][3], areg[0][0], q1.z, q1.w);
                MMA_INIT(acc[1][2], areg[1][0], q1.x, q1.y); MMA_INIT(acc[1][3], areg[1][0], q1.z, q1.w);
            } else {
                MMA(acc[0][0], areg[0][s], q0.x, q0.y); MMA(acc[0][1], areg[0][s], q0.z, q0.w);
                MMA(acc[1][0], areg[1][s], q0.x, q0.y); MMA(acc[1][1], areg[1][s], q0.z, q0.w);
                MMA(acc[0][2], areg[0][s], q1.x, q1.y); MMA(acc[0][3], areg[0][s], q1.z, q1.w);
                MMA(acc[1][2], areg[1][s], q1.x, q1.y); MMA(acc[1][3], areg[1][s], q1.z, q1.w);
            }
        }

        // ---- epilogue ----
        if (t == t_diag) {                  // exact fp32 path (1/32 stages)
#pragma unroll
            for (int mt = 0; mt < 2; mt++) {
#pragma unroll
                for (int nt = 0; nt < 4; nt++) {
                    const int col = t * 64 + wn * 32 + nt * 8 + t4 * 2;
                    float* A4 = acc[mt][nt];
                    float v, l;
                    v = A4[0]; l = fmaf(w2, v, b2);
                    if (col == sp0[mt])     { l = fmaf(wd, v, bd); s_tgt[lrow[mt]] = l; }
                    rsum[mt][0] += ex2(l);
                    v = A4[1]; l = fmaf(w2, v, b2);
                    if (col + 1 == sp0[mt]) { l = fmaf(wd, v, bd); s_tgt[lrow[mt]] = l; }
                    rsum[mt][0] += ex2(l);
                    v = A4[2]; l = fmaf(w2, v, b2);
                    if (col == sp1[mt])     { l = fmaf(wd, v, bd); s_tgt[lrow[mt] + 8] = l; }
                    rsum[mt][1] += ex2(l);
                    v = A4[3]; l = fmaf(w2, v, b2);
                    if (col + 1 == sp1[mt]) { l = fmaf(wd, v, bd); s_tgt[lrow[mt] + 8] = l; }
                    rsum[mt][1] += ex2(l);
                }
            }
        } else {                            // f16x2 fast path (31/32 stages)
#pragma unroll
            for (int mt = 0; mt < 2; mt++) {
                uint32_t t0 = 0u, t1 = 0u;   // f16x2 partials, rows g and g+8
#pragma unroll
                for (int nt = 0; nt < 4; nt++) {
                    float* A4 = acc[mt][nt];
                    t0 = hadd2(t0, ex2h2(hfma2(w2h, cvt2h(A4[0], A4[1]), b2h)));
                    t1 = hadd2(t1, ex2h2(hfma2(w2h, cvt2h(A4[2], A4[3]), b2h)));
                }
                rsum[mt][0] += hsum2(t0);
                rsum[mt][1] += hsum2(t1);
            }
        }
    }

    // reduce 4 t4-lanes per row, then the 2 n-warps
#pragma unroll
    for (int mt = 0; mt < 2; mt++)
#pragma unroll
        for (int hh = 0; hh < 2; hh++) {
            float v = rsum[mt][hh];
            v += __shfl_xor_sync(0xFFFFFFFFu, v, 1);
            v += __shfl_xor_sync(0xFFFFFFFFu, v, 2);
            if (t4 == 0) s_red[lrow[mt] + hh * 8][wn] = v;
        }
    __syncthreads();
    if (tid < BM) {
        float S = s_red[tid][0] + s_red[tid][1];
        s_loss[tid] = (log2f(S) - s_tgt[tid]) * 0.69314718055994531f;
    }
    __syncthreads();
    if (tid == 0) {
        float L = 0.f;
#pragma unroll 8
        for (int r = 0; r < BM; r++) L += s_loss[r];
        g_partial[blockIdx.x] = L;
        __threadfence();
        unsigned old = atomicAdd(&g_ctr, 1u);
        s_last = (old == NCTA - 1);
    }
    __syncthreads();

    if (s_last) {                           // deterministic final reduce (512 partials)
        if (tid == 0) g_ctr = 0;
        __threadfence();
        float v = g_partial[tid] + g_partial[tid + 128]
                + g_partial[tid + 256] + g_partial[tid + 384];
        __shared__ float s_fin[128];
        s_fin[tid] = v;
        __syncthreads();
        for (int o = 64; o > 0; o >>= 1) {
            if (tid < o) s_fin[tid] += s_fin[tid + o];
            __syncthreads();
        }
        if (tid == 0) out[0] = s_fin[0] * (1.0f / (float)ROWS);
    }
}

extern "C" void kernel_launch(void* const* d_in, const int* in_sizes, int n_in,
                              void* d_out, int out_size) {
    const float* x = (const float*)d_in[0];
    const float* w = (const float*)d_in[1];
    const float* b = (const float*)d_in[2];
    float* out = (float*)d_out;

    cudaFuncSetAttribute(ge2e_main, cudaFuncAttributeMaxDynamicSharedMemorySize, DYN_SMEM);

    pack_ab_kernel<<<2048 + 128, 256>>>(x);
    ge2e_main<<<NCTA, THREADS, DYN_SMEM>>>(w, b, out);
}

// round 12
// speedup vs baseline: 1.0930x; 1.0930x over previous
#include <cuda_runtime.h>
#include <cuda_fp16.h>
#include <cstdint>
#include <math.h>

#define N_SPK 2048
#define M_UTT 16
#define D_DIM 128
#define ROWS  32768

#define BM 256                  // rows per CTA
#define NCTA (ROWS / BM)        // 128 -> single wave, all resident
#define NSTAGE 32               // 64-col stages over N_SPK
#define THREADS 512

#define A_U4 (16 * 8 * 32)      // per-CTA packed A uint4 = 4096
#define STG_U4 1024             // 16KB per full 64-col stage (in gBh)
#define GRP_BYTES 8192          // half-stage (16 rows) per n-group
#define DYN_SMEM (2 * 2 * GRP_BYTES)   // 32KB: 2 groups x double buffer

// packed fp16 operands in fragment order (__device__ scratch; no cudaMalloc)
__device__ uint4 gAh[NCTA * A_U4];               // 8MB
__device__ uint4 gBh[NSTAGE * STG_U4];           // 512KB
__device__ float g_partial[NCTA];
__device__ unsigned g_ctr = 0;

// ---------------------------------------------------------------------------
__device__ __forceinline__ void cp_async16(uint32_t dst, const void* src) {
    asm volatile("cp.async.cg.shared.global [%0], [%1], 16;" :: "r"(dst), "l"(src));
}
__device__ __forceinline__ uint32_t smem_u32(const void* p) {
    uint32_t a;
    asm("{ .reg .u64 t; cvta.to.shared.u64 t, %1; cvt.u32.u64 %0, t; }" : "=r"(a) : "l"(p));
    return a;
}
#define CP_COMMIT() asm volatile("cp.async.commit_group;" ::: "memory")
#define CP_WAIT0()  asm volatile("cp.async.wait_group 0;" ::: "memory")
#define GRP_BAR(id) asm volatile("bar.sync %0, %1;" :: "r"(id), "r"(256) : "memory")

__device__ __forceinline__ uint32_t pack2(float lo, float hi) {
    __half2 h = __floats2half2_rn(lo, hi);
    return *reinterpret_cast<uint32_t*>(&h);
}
__device__ __forceinline__ float ex2(float x) {
    float y;
    asm("ex2.approx.f32 %0, %1;" : "=f"(y) : "f"(x));
    return y;
}

#define MMA(d, a, b0, b1) \
    asm volatile("mma.sync.aligned.m16n8k16.row.col.f32.f16.f16.f32 " \
                 "{%0,%1,%2,%3},{%4,%5,%6,%7},{%8,%9},{%0,%1,%2,%3};" \
                 : "+f"((d)[0]), "+f"((d)[1]), "+f"((d)[2]), "+f"((d)[3]) \
                 : "r"((a).x), "r"((a).y), "r"((a).z), "r"((a).w), "r"(b0), "r"(b1))
#define MMA_INIT(d, a, b0, b1) \
    asm volatile("mma.sync.aligned.m16n8k16.row.col.f32.f16.f16.f32 " \
                 "{%0,%1,%2,%3},{%4,%5,%6,%7},{%8,%9},{%10,%10,%10,%10};" \
                 : "=f"((d)[0]), "=f"((d)[1]), "=f"((d)[2]), "=f"((d)[3]) \
                 : "r"((a).x), "r"((a).y), "r"((a).z), "r"((a).w), "r"(b0), "r"(b1), "f"(0.f))

// ---------------------------------------------------------------------------
// Fused pre-pack: blocks [0,2048) pack A; blocks [2048,2176) pack B.
// A: id = [cta7][mt4][ks3][lane5]   (BM=256 -> 16 m-tiles)
// B: id = [t5][ks3][pp2][lane5]
// ---------------------------------------------------------------------------
__global__ __launch_bounds__(256) void pack_ab_kernel(const float* __restrict__ x) {
    if (blockIdx.x < 2048) {
        int id = blockIdx.x * 256 + threadIdx.x;        // 0..524287
        int lane = id & 31, ks = (id >> 5) & 7, mt = (id >> 8) & 15, cta = id >> 12;
        int g = lane >> 2, t = lane & 3;
        int r0 = cta * BM + mt * 16 + g;
        int k0 = ks * 16 + t * 2;
        const float* p0 = x + (size_t)r0 * D_DIM;
        const float* p1 = p0 + 8 * D_DIM;
        float2 alo = *(const float2*)(p0 + k0);
        float2 blo = *(const float2*)(p1 + k0);
        float2 ahi = *(const float2*)(p0 + k0 + 8);
        float2 bhi = *(const float2*)(p1 + k0 + 8);
        uint4 o;
        o.x = pack2(alo.x, alo.y);
        o.y = pack2(blo.x, blo.y);
        o.z = pack2(ahi.x, ahi.y);
        o.w = pack2(bhi.x, bhi.y);
        gAh[id] = o;
    } else {
        int id = (blockIdx.x - 2048) * 256 + threadIdx.x;   // 0..32767
        int lane = id & 31, pp = (id >> 5) & 3, ks = (id >> 7) & 7, t = id >> 10;
        int g = lane >> 2, tt = lane & 3;
        int col0 = t * 64 + pp * 16 + g;
        int k0 = ks * 16 + tt * 2;
        const float* base0 = x + (size_t)col0 * M_UTT * D_DIM;
        const float* base1 = base0 + (size_t)8 * M_UTT * D_DIM;
        float2 s0l = {0.f, 0.f}, s0h = {0.f, 0.f}, s1l = {0.f, 0.f}, s1h = {0.f, 0.f};
#pragma unroll
        for (int m = 0; m < M_UTT; m++) {
            const float* r0 = base0 + m * D_DIM;
            const float* r1 = base1 + m * D_DIM;
            float2 v;
            v = *(const float2*)(r0 + k0);     s0l.x += v.x; s0l.y += v.y;
            v = *(const float2*)(r0 + k0 + 8); s0h.x += v.x; s0h.y += v.y;
            v = *(const float2*)(r1 + k0);     s1l.x += v.x; s1l.y += v.y;
            v = *(const float2*)(r1 + k0 + 8); s1h.x += v.x; s1h.y += v.y;
        }
        const float inv = 1.0f / M_UTT;
        uint4 o;
        o.x = pack2(s0l.x * inv, s0l.y * inv);
        o.y = pack2(s0h.x * inv, s0h.y * inv);
        o.z = pack2(s1l.x * inv, s1l.y * inv);
        o.w = pack2(s1h.x * inv, s1h.y * inv);
        gBh[id] = o;
    }
}

// ---------------------------------------------------------------------------
// group loader: n-group ng (256 threads, group-linear id gl) loads its 16 rows
// (pp = 2ng, 2ng+1 for s = 0..7) of stage t into its private buffer.
// buffer layout: [row_local = s*2 + jj][lane]
// ---------------------------------------------------------------------------
__device__ __forceinline__ void load_group_stage(uint32_t grpBase, int t, int ng, int gl) {
    const uint4* src = gBh + (size_t)t * STG_U4;
    uint32_t dst = grpBase + (t & 1) * GRP_BYTES;
#pragma unroll
    for (int j = 0; j < 2; j++) {
        int idx = gl + j * 256;             // 0..511
        int row_local = idx >> 5;           // 0..15
        int l = idx & 31;
        int s  = row_local >> 1;
        int jj = row_local & 1;
        int srow = s * 4 + 2 * ng + jj;     // row in the full 32-row stage
        cp_async16(dst + idx * 16, src + srow * 32 + l);
    }
}

// ---------------------------------------------------------------------------
// Main: fp16 mma.sync GEMM + log2-softmax. BM=256, 512 thr, grid=128:
// all CTAs resident (single wave). 16 warps = 8(m) x 2(n); each n-group is an
// independent named-barrier pipeline (no CTA-wide sync in the main loop).
// A in registers (64/thread); B in 2 private double buffers (32KB total).
// ---------------------------------------------------------------------------
__global__ __launch_bounds__(THREADS, 1) void ge2e_main(const float* __restrict__ wp,
                                                        const float* __restrict__ bp,
                                                        float* __restrict__ out) {
    extern __shared__ uint4 dsm[];
    __shared__ float s_tgt[BM];
    __shared__ float s_red[BM][2];
    __shared__ float s_loss[BM];
    __shared__ bool  s_last;

    const int tid  = threadIdx.x;
    const int wid  = tid >> 5;
    const int lane = tid & 31;
    const int mg = wid >> 1;            // 0..7  (m-group: rows mg*32..mg*32+31)
    const int ng = wid & 1;             // 0..1  (n-group / pipeline id)
    const int gl = mg * 32 + lane;      // group-linear id 0..255
    const int g  = lane >> 2;
    const int t4 = lane & 3;

    const float L2E = 1.44269504088896341f;
    const float w2  = wp[0] * L2E;
    const float b2  = bp[0] * L2E;
    const float wd  = w2 * (16.0f / 15.0f);
    const float bd  = b2 - w2 * (1.0f / 15.0f);

    const uint32_t grpBase = smem_u32(dsm) + ng * (2 * GRP_BYTES);
    const int t_diag = blockIdx.x >> 2;     // stage holding this CTA's self cols

    // stage0 copy first; overlaps the A register loads
    load_group_stage(grpBase, 0, ng, gl);
    CP_COMMIT();

    // A -> registers (64 regs), reused for all 32 stages
    uint4 areg[2][8];
    {
        const uint4* gAs = gAh + (size_t)blockIdx.x * A_U4;
#pragma unroll
        for (int i = 0; i < 2; i++)
#pragma unroll
            for (int s = 0; s < 8; s++)
                areg[i][s] = gAs[((mg * 2 + i) * 8 + s) * 32 + lane];
    }

    float acc[2][4][4];
    float rsum[2][2] = {};
    int lrow[2], sp0[2], sp1[2];
#pragma unroll
    for (int mt = 0; mt < 2; mt++) {
        lrow[mt] = mg * 32 + mt * 16 + g;
        int gr = blockIdx.x * BM + lrow[mt];
        sp0[mt] = gr >> 4;
        sp1[mt] = (gr + 8) >> 4;
    }

    for (int t = 0; t < NSTAGE; t++) {
        CP_WAIT0();                 // my cp.asyncs for stage t done
        GRP_BAR(ng + 1);            // whole group's copies visible; old buf free
        if (t + 1 < NSTAGE) {
            load_group_stage(grpBase, t + 1, ng, gl);
            CP_COMMIT();
        }

        const uint4* Bst = dsm + (ng * 2 + (t & 1)) * (GRP_BYTES / 16);

        // ---- MMA: 8 k-steps, A from registers, 2 LDS.128 per step ----
#pragma unroll
        for (int s = 0; s < 8; s++) {
            uint4 q0 = Bst[(s * 2 + 0) * 32 + lane];
            uint4 q1 = Bst[(s * 2 + 1) * 32 + lane];
            if (s == 0) {
                MMA_INIT(acc[0][0], areg[0][0], q0.x, q0.y); MMA_INIT(acc[0][1], areg[0][0], q0.z, q0.w);
                MMA_INIT(acc[1][0], areg[1][0], q0.x, q0.y); MMA_INIT(acc[1][1], areg[1][0], q0.z, q0.w);
                MMA_INIT(acc[0][2], areg[0][0], q1.x, q1.y); MMA_INIT(acc[0][3], areg[0][0], q1.z, q1.w);
                MMA_INIT(acc[1][2], areg[1][0], q1.x, q1.y); MMA_INIT(acc[1][3], areg[1][0], q1.z, q1.w);
            } else {
                MMA(acc[0][0], areg[0][s], q0.x, q0.y); MMA(acc[0][1], areg[0][s], q0.z, q0.w);
                MMA(acc[1][0], areg[1][s], q0.x, q0.y); MMA(acc[1][1], areg[1][s], q0.z, q0.w);
                MMA(acc[0][2], areg[0][s], q1.x, q1.y); MMA(acc[0][3], areg[0][s], q1.z, q1.w);
                MMA(acc[1][2], areg[1][s], q1.x, q1.y); MMA(acc[1][3], areg[1][s], q1.z, q1.w);
            }
        }

        // ---- epilogue (fp32 exact; no barrier -> overlaps other pipeline) ----
        if (t == t_diag) {                  // the one stage with self-speaker cols
#pragma unroll
            for (int mt = 0; mt < 2; mt++) {
#pragma unroll
                for (int nt = 0; nt < 4; nt++) {
                    const int col = t * 64 + ng * 32 + nt * 8 + t4 * 2;
                    float* A4 = acc[mt][nt];
                    float v, l;
                    v = A4[0]; l = fmaf(w2, v, b2);
                    if (col == sp0[mt])     { l = fmaf(wd, v, bd); s_tgt[lrow[mt]] = l; }
                    rsum[mt][0] += ex2(l);
                    v = A4[1]; l = fmaf(w2, v, b2);
                    if (col + 1 == sp0[mt]) { l = fmaf(wd, v, bd); s_tgt[lrow[mt]] = l; }
                    rsum[mt][0] += ex2(l);
                    v = A4[2]; l = fmaf(w2, v, b2);
                    if (col == sp1[mt])     { l = fmaf(wd, v, bd); s_tgt[lrow[mt] + 8] = l; }
                    rsum[mt][1] += ex2(l);
                    v = A4[3]; l = fmaf(w2, v, b2);
                    if (col + 1 == sp1[mt]) { l = fmaf(wd, v, bd); s_tgt[lrow[mt] + 8] = l; }
                    rsum[mt][1] += ex2(l);
                }
            }
        } else {                            // compare-free (31/32 stages)
#pragma unroll
            for (int mt = 0; mt < 2; mt++) {
                float r0 = 0.f, r1 = 0.f;
#pragma unroll
                for (int nt = 0; nt < 4; nt++) {
                    float* A4 = acc[mt][nt];
                    r0 += ex2(fmaf(w2, A4[0], b2));
                    r0 += ex2(fmaf(w2, A4[1], b2));
                    r1 += ex2(fmaf(w2, A4[2], b2));
                    r1 += ex2(fmaf(w2, A4[3], b2));
                }
                rsum[mt][0] += r0;
                rsum[mt][1] += r1;
            }
        }
    }

    // reduce 4 t4-lanes per row, then the 2 n-groups
#pragma unroll
    for (int mt = 0; mt < 2; mt++)
#pragma unroll
        for (int hh = 0; hh < 2; hh++) {
            float v = rsum[mt][hh];
            v += __shfl_xor_sync(0xFFFFFFFFu, v, 1);
            v += __shfl_xor_sync(0xFFFFFFFFu, v, 2);
            if (t4 == 0) s_red[lrow[mt] + hh * 8][ng] = v;
        }
    __syncthreads();
    if (tid < BM) {
        float S = s_red[tid][0] + s_red[tid][1];
        s_loss[tid] = (log2f(S) - s_tgt[tid]) * 0.69314718055994531f;
    }
    __syncthreads();
    for (int o = 128; o > 0; o >>= 1) {     // tree-reduce 256 row losses
        if (tid < o) s_loss[tid] += s_loss[tid + o];
        __syncthreads();
    }
    if (tid == 0) {
        g_partial[blockIdx.x] = s_loss[0];
        __threadfence();
        unsigned old = atomicAdd(&g_ctr, 1u);
        s_last = (old == NCTA - 1);
    }
    __syncthreads();

    if (s_last) {                           // deterministic final reduce (128 partials)
        if (tid == 0) g_ctr = 0;
        __threadfence();
        if (tid < NCTA) s_loss[tid] = g_partial[tid];
        __syncthreads();
        for (int o = NCTA / 2; o > 0; o >>= 1) {
            if (tid < o) s_loss[tid] += s_loss[tid + o];
            __syncthreads();
        }
        if (tid == 0) out[0] = s_loss[0] * (1.0f / (float)ROWS);
    }
}

extern "C" void kernel_launch(void* const* d_in, const int* in_sizes, int n_in,
                              void* d_out, int out_size) {
    const float* x = (const float*)d_in[0];
    const float* w = (const float*)d_in[1];
    const float* b = (const float*)d_in[2];
    float* out = (float*)d_out;

    cudaFuncSetAttribute(ge2e_main, cudaFuncAttributeMaxDynamicSharedMemorySize, DYN_SMEM);

    pack_ab_kernel<<<2048 + 128, 256>>>(x);
    ge2e_main<<<NCTA, THREADS, DYN_SMEM>>>(w, b, out);
}

// round 13
// speedup vs baseline: 1.1424x; 1.0452x over previous
#include <cuda_runtime.h>
#include <cuda_fp16.h>
#include <cstdint>
#include <math.h>

#define N_SPK 2048
#define M_UTT 16
#define D_DIM 128
#define ROWS  32768

#define BM 256                  // rows per CTA
#define NCTA (ROWS / BM)        // 128 -> single wave, all resident
#define NSTAGE 32               // 64-col stages over N_SPK
#define THREADS 512

#define A_U4 (16 * 8 * 32)      // per-CTA packed A uint4 = 4096
#define STG_U4 1024             // 16KB per full 64-col stage (in gBh)
#define GRP_BYTES 8192          // half-stage (16 rows) per n-group
#define DYN_SMEM (2 * 2 * GRP_BYTES)   // 32KB: 2 groups x double buffer

// packed fp16 operands in fragment order (__device__ scratch; no cudaMalloc)
__device__ uint4 gAh[NCTA * A_U4];               // 8MB
__device__ uint4 gBh[NSTAGE * STG_U4];           // 512KB
__device__ float g_partial[NCTA];
__device__ unsigned g_ctr = 0;

// ---------------------------------------------------------------------------
__device__ __forceinline__ void cp_async16(uint32_t dst, const void* src) {
    asm volatile("cp.async.cg.shared.global [%0], [%1], 16;" :: "r"(dst), "l"(src));
}
__device__ __forceinline__ uint32_t smem_u32(const void* p) {
    uint32_t a;
    asm("{ .reg .u64 t; cvta.to.shared.u64 t, %1; cvt.u32.u64 %0, t; }" : "=r"(a) : "l"(p));
    return a;
}
#define CP_COMMIT() asm volatile("cp.async.commit_group;" ::: "memory")
#define CP_WAIT0()  asm volatile("cp.async.wait_group 0;" ::: "memory")
#define GRP_BAR(id) asm volatile("bar.sync %0, %1;" :: "r"(id), "r"(256) : "memory")

__device__ __forceinline__ uint32_t pack2(float lo, float hi) {
    __half2 h = __floats2half2_rn(lo, hi);
    return *reinterpret_cast<uint32_t*>(&h);
}
__device__ __forceinline__ float ex2(float x) {
    float y;
    asm("ex2.approx.f32 %0, %1;" : "=f"(y) : "f"(x));
    return y;
}
// ---- f16x2 epilogue helpers ----
__device__ __forceinline__ uint32_t cvt2h(float a, float b) {
    uint32_t d;
    asm("cvt.rn.f16x2.f32 %0, %1, %2;" : "=r"(d) : "f"(b), "f"(a));
    return d;
}
__device__ __forceinline__ uint32_t hfma2(uint32_t a, uint32_t b, uint32_t c) {
    uint32_t d;
    asm("fma.rn.f16x2 %0, %1, %2, %3;" : "=r"(d) : "r"(a), "r"(b), "r"(c));
    return d;
}
__device__ __forceinline__ uint32_t ex2h2(uint32_t a) {
    uint32_t d;
    asm("ex2.approx.f16x2 %0, %1;" : "=r"(d) : "r"(a));
    return d;
}
__device__ __forceinline__ uint32_t hadd2(uint32_t a, uint32_t b) {
    uint32_t d;
    asm("add.rn.f16x2 %0, %1, %2;" : "=r"(d) : "r"(a), "r"(b));
    return d;
}
__device__ __forceinline__ float hsum2(uint32_t v) {
    float lo, hi;
    asm("{ .reg .b16 l, h; mov.b32 {l, h}, %2; cvt.f32.f16 %0, l; cvt.f32.f16 %1, h; }"
        : "=f"(lo), "=f"(hi) : "r"(v));
    return lo + hi;
}

#define MMA(d, a, b0, b1) \
    asm volatile("mma.sync.aligned.m16n8k16.row.col.f32.f16.f16.f32 " \
                 "{%0,%1,%2,%3},{%4,%5,%6,%7},{%8,%9},{%0,%1,%2,%3};" \
                 : "+f"((d)[0]), "+f"((d)[1]), "+f"((d)[2]), "+f"((d)[3]) \
                 : "r"((a).x), "r"((a).y), "r"((a).z), "r"((a).w), "r"(b0), "r"(b1))
#define MMA_INIT(d, a, b0, b1) \
    asm volatile("mma.sync.aligned.m16n8k16.row.col.f32.f16.f16.f32 " \
                 "{%0,%1,%2,%3},{%4,%5,%6,%7},{%8,%9},{%10,%10,%10,%10};" \
                 : "=f"((d)[0]), "=f"((d)[1]), "=f"((d)[2]), "=f"((d)[3]) \
                 : "r"((a).x), "r"((a).y), "r"((a).z), "r"((a).w), "r"(b0), "r"(b1), "f"(0.f))

// ---------------------------------------------------------------------------
// Fused pre-pack: blocks [0,2048) pack A; blocks [2048,2176) pack B.
// ---------------------------------------------------------------------------
__global__ __launch_bounds__(256) void pack_ab_kernel(const float* __restrict__ x) {
    if (blockIdx.x < 2048) {
        int id = blockIdx.x * 256 + threadIdx.x;        // 0..524287
        int lane = id & 31, ks = (id >> 5) & 7, mt = (id >> 8) & 15, cta = id >> 12;
        int g = lane >> 2, t = lane & 3;
        int r0 = cta * BM + mt * 16 + g;
        int k0 = ks * 16 + t * 2;
        const float* p0 = x + (size_t)r0 * D_DIM;
        const float* p1 = p0 + 8 * D_DIM;
        float2 alo = *(const float2*)(p0 + k0);
        float2 blo = *(const float2*)(p1 + k0);
        float2 ahi = *(const float2*)(p0 + k0 + 8);
        float2 bhi = *(const float2*)(p1 + k0 + 8);
        uint4 o;
        o.x = pack2(alo.x, alo.y);
        o.y = pack2(blo.x, blo.y);
        o.z = pack2(ahi.x, ahi.y);
        o.w = pack2(bhi.x, bhi.y);
        gAh[id] = o;
    } else {
        int id = (blockIdx.x - 2048) * 256 + threadIdx.x;   // 0..32767
        int lane = id & 31, pp = (id >> 5) & 3, ks = (id >> 7) & 7, t = id >> 10;
        int g = lane >> 2, tt = lane & 3;
        int col0 = t * 64 + pp * 16 + g;
        int k0 = ks * 16 + tt * 2;
        const float* base0 = x + (size_t)col0 * M_UTT * D_DIM;
        const float* base1 = base0 + (size_t)8 * M_UTT * D_DIM;
        float2 s0l = {0.f, 0.f}, s0h = {0.f, 0.f}, s1l = {0.f, 0.f}, s1h = {0.f, 0.f};
#pragma unroll
        for (int m = 0; m < M_UTT; m++) {
            const float* r0 = base0 + m * D_DIM;
            const float* r1 = base1 + m * D_DIM;
            float2 v;
            v = *(const float2*)(r0 + k0);     s0l.x += v.x; s0l.y += v.y;
            v = *(const float2*)(r0 + k0 + 8); s0h.x += v.x; s0h.y += v.y;
            v = *(const float2*)(r1 + k0);     s1l.x += v.x; s1l.y += v.y;
            v = *(const float2*)(r1 + k0 + 8); s1h.x += v.x; s1h.y += v.y;
        }
        const float inv = 1.0f / M_UTT;
        uint4 o;
        o.x = pack2(s0l.x * inv, s0l.y * inv);
        o.y = pack2(s0h.x * inv, s0h.y * inv);
        o.z = pack2(s1l.x * inv, s1l.y * inv);
        o.w = pack2(s1h.x * inv, s1h.y * inv);
        gBh[id] = o;
    }
}

// ---------------------------------------------------------------------------
// group loader: n-group ng loads its 16 rows of stage t into its private buf
// ---------------------------------------------------------------------------
__device__ __forceinline__ void load_group_stage(uint32_t grpBase, int t, int ng, int gl) {
    const uint4* src = gBh + (size_t)t * STG_U4;
    uint32_t dst = grpBase + (t & 1) * GRP_BYTES;
#pragma unroll
    for (int j = 0; j < 2; j++) {
        int idx = gl + j * 256;             // 0..511
        int row_local = idx >> 5;           // 0..15
        int l = idx & 31;
        int s  = row_local >> 1;
        int jj = row_local & 1;
        int srow = s * 4 + 2 * ng + jj;     // row in the full 32-row stage
        cp_async16(dst + idx * 16, src + srow * 32 + l);
    }
}

// ---------------------------------------------------------------------------
// Main: fp16 mma.sync GEMM + log2-softmax. grid=128 single wave; 16 warps =
// 8(m) x 2(n); two independent named-barrier pipelines. A in registers;
// B in private double buffers. f16x2 epilogue on the 31/32 non-diag stages.
// ---------------------------------------------------------------------------
__global__ __launch_bounds__(THREADS, 1) void ge2e_main(const float* __restrict__ wp,
                                                        const float* __restrict__ bp,
                                                        float* __restrict__ out) {
    extern __shared__ uint4 dsm[];
    __shared__ float s_tgt[BM];
    __shared__ float s_red[BM][2];
    __shared__ float s_loss[BM];
    __shared__ bool  s_last;

    const int tid  = threadIdx.x;
    const int wid  = tid >> 5;
    const int lane = tid & 31;
    const int mg = wid >> 1;            // 0..7
    const int ng = wid & 1;             // 0..1
    const int gl = mg * 32 + lane;      // group-linear id 0..255
    const int g  = lane >> 2;
    const int t4 = lane & 3;

    const float L2E = 1.44269504088896341f;
    const float w2  = wp[0] * L2E;
    const float b2  = bp[0] * L2E;
    const float wd  = w2 * (16.0f / 15.0f);
    const float bd  = b2 - w2 * (1.0f / 15.0f);
    const uint32_t w2h = pack2(w2, w2);
    const uint32_t b2h = pack2(b2, b2);

    const uint32_t grpBase = smem_u32(dsm) + ng * (2 * GRP_BYTES);
    const int t_diag = blockIdx.x >> 2;

    load_group_stage(grpBase, 0, ng, gl);
    CP_COMMIT();

    // A -> registers (64 regs), reused for all 32 stages
    uint4 areg[2][8];
    {
        const uint4* gAs = gAh + (size_t)blockIdx.x * A_U4;
#pragma unroll
        for (int i = 0; i < 2; i++)
#pragma unroll
            for (int s = 0; s < 8; s++)
                areg[i][s] = gAs[((mg * 2 + i) * 8 + s) * 32 + lane];
    }

    float acc[2][4][4];
    float rsum[2][2] = {};
    int lrow[2], sp0[2], sp1[2];
#pragma unroll
    for (int mt = 0; mt < 2; mt++) {
        lrow[mt] = mg * 32 + mt * 16 + g;
        int gr = blockIdx.x * BM + lrow[mt];
        sp0[mt] = gr >> 4;
        sp1[mt] = (gr + 8) >> 4;
    }

    for (int t = 0; t < NSTAGE; t++) {
        CP_WAIT0();
        GRP_BAR(ng + 1);
        if (t + 1 < NSTAGE) {
            load_group_stage(grpBase, t + 1, ng, gl);
            CP_COMMIT();
        }

        const uint4* Bst = dsm + (ng * 2 + (t & 1)) * (GRP_BYTES / 16);

        // ---- MMA: 8 k-steps, A from registers, 2 LDS.128 per step ----
#pragma unroll
        for (int s = 0; s < 8; s++) {
            uint4 q0 = Bst[(s * 2 + 0) * 32 + lane];
            uint4 q1 = Bst[(s * 2 + 1) * 32 + lane];
            if (s == 0) {
                MMA_INIT(acc[0][0], areg[0][0], q0.x, q0.y); MMA_INIT(acc[0][1], areg[0][0], q0.z, q0.w);
                MMA_INIT(acc[1][0], areg[1][0], q0.x, q0.y); MMA_INIT(acc[1][1], areg[1][0], q0.z, q0.w);
                MMA_INIT(acc[0][2], areg[0][0], q1.x, q1.y); MMA_INIT(acc[0][3], areg[0][0], q1.z, q1.w);
                MMA_INIT(acc[1][2], areg[1][0], q1.x, q1.y); MMA_INIT(acc[1][3], areg[1][0], q1.z, q1.w);
            } else {
                MMA(acc[0][0], areg[0][s], q0.x, q0.y); MMA(acc[0][1], areg[0][s], q0.z, q0.w);
                MMA(acc[1][0], areg[1][s], q0.x, q0.y); MMA(acc[1][1], areg[1][s], q0.z, q0.w);
                MMA(acc[0][2], areg[0][s], q1.x, q1.y); MMA(acc[0][3], areg[0][s], q1.z, q1.w);
                MMA(acc[1][2], areg[1][s], q1.x, q1.y); MMA(acc[1][3], areg[1][s], q1.z, q1.w);
            }
        }

        // ---- epilogue (no barrier -> overlaps other pipeline's MMAs) ----
        if (t == t_diag) {                  // exact fp32 path (1/32 stages)
#pragma unroll
            for (int mt = 0; mt < 2; mt++) {
#pragma unroll
                for (int nt = 0; nt < 4; nt++) {
                    const int col = t * 64 + ng * 32 + nt * 8 + t4 * 2;
                    float* A4 = acc[mt][nt];
                    float v, l;
                    v = A4[0]; l = fmaf(w2, v, b2);
                    if (col == sp0[mt])     { l = fmaf(wd, v, bd); s_tgt[lrow[mt]] = l; }
                    rsum[mt][0] += ex2(l);
                    v = A4[1]; l = fmaf(w2, v, b2);
                    if (col + 1 == sp0[mt]) { l = fmaf(wd, v, bd); s_tgt[lrow[mt]] = l; }
                    rsum[mt][0] += ex2(l);
                    v = A4[2]; l = fmaf(w2, v, b2);
                    if (col == sp1[mt])     { l = fmaf(wd, v, bd); s_tgt[lrow[mt] + 8] = l; }
                    rsum[mt][1] += ex2(l);
                    v = A4[3]; l = fmaf(w2, v, b2);
                    if (col + 1 == sp1[mt]) { l = fmaf(wd, v, bd); s_tgt[lrow[mt] + 8] = l; }
                    rsum[mt][1] += ex2(l);
                }
            }
        } else {                            // f16x2 fast path (31/32 stages)
#pragma unroll
            for (int mt = 0; mt < 2; mt++) {
                uint32_t h0 = 0u, h1 = 0u;   // f16x2 partials, rows g and g+8
#pragma unroll
                for (int nt = 0; nt < 4; nt++) {
                    float* A4 = acc[mt][nt];
                    h0 = hadd2(h0, ex2h2(hfma2(w2h, cvt2h(A4[0], A4[1]), b2h)));
                    h1 = hadd2(h1, ex2h2(hfma2(w2h, cvt2h(A4[2], A4[3]), b2h)));
                }
                rsum[mt][0] += hsum2(h0);
                rsum[mt][1] += hsum2(h1);
            }
        }
    }

    // reduce 4 t4-lanes per row, then the 2 n-groups
#pragma unroll
    for (int mt = 0; mt < 2; mt++)
#pragma unroll
        for (int hh = 0; hh < 2; hh++) {
            float v = rsum[mt][hh];
            v += __shfl_xor_sync(0xFFFFFFFFu, v, 1);
            v += __shfl_xor_sync(0xFFFFFFFFu, v, 2);
            if (t4 == 0) s_red[lrow[mt] + hh * 8][ng] = v;
        }
    __syncthreads();
    if (tid < BM) {
        float S = s_red[tid][0] + s_red[tid][1];
        s_loss[tid] = (log2f(S) - s_tgt[tid]) * 0.69314718055994531f;
    }
    __syncthreads();
    for (int o = 128; o > 0; o >>= 1) {
        if (tid < o) s_loss[tid] += s_loss[tid + o];
        __syncthreads();
    }
    if (tid == 0) {
        g_partial[blockIdx.x] = s_loss[0];
        __threadfence();
        unsigned old = atomicAdd(&g_ctr, 1u);
        s_last = (old == NCTA - 1);
    }
    __syncthreads();

    if (s_last) {
        if (tid == 0) g_ctr = 0;
        __threadfence();
        if (tid < NCTA) s_loss[tid] = g_partial[tid];
        __syncthreads();
        for (int o = NCTA / 2; o > 0; o >>= 1) {
            if (tid < o) s_loss[tid] += s_loss[tid + o];
            __syncthreads();
        }
        if (tid == 0) out[0] = s_loss[0] * (1.0f / (float)ROWS);
    }
}

extern "C" void kernel_launch(void* const* d_in, const int* in_sizes, int n_in,
                              void* d_out, int out_size) {
    const float* x = (const float*)d_in[0];
    const float* w = (const float*)d_in[1];
    const float* b = (const float*)d_in[2];
    float* out = (float*)d_out;

    cudaFuncSetAttribute(ge2e_main, cudaFuncAttributeMaxDynamicSharedMemorySize, DYN_SMEM);

    pack_ab_kernel<<<2048 + 128, 256>>>(x);
    ge2e_main<<<NCTA, THREADS, DYN_SMEM>>>(w, b, out);
}

// round 14
// speedup vs baseline: 1.2021x; 1.0522x over previous
#include <cuda_runtime.h>
#include <cuda_fp16.h>
#include <cstdint>
#include <math.h>

#define N_SPK 2048
#define M_UTT 16
#define D_DIM 128
#define ROWS  32768

#define BM 256                  // rows per CTA
#define NCTA (ROWS / BM)        // 128 -> single wave, all resident
#define NSTAGE 32               // 64-col stages over N_SPK
#define THREADS 512

#define A_U4 (16 * 8 * 32)      // per-CTA packed A uint4 = 4096
#define STG_U4 1024             // 16KB per full 64-col stage (in gBh)
#define GRP_BYTES 8192          // half-stage (16 rows) per n-group
#define DYN_SMEM (2 * 2 * GRP_BYTES)   // 32KB: 2 groups x double buffer

// packed fp16 operands in fragment order (__device__ scratch; no cudaMalloc)
__device__ uint4 gAh[NCTA * A_U4];               // 8MB
__device__ uint4 gBh[NSTAGE * STG_U4];           // 512KB
__device__ float g_partial[NCTA];
__device__ unsigned g_ctr = 0;

// ---------------------------------------------------------------------------
__device__ __forceinline__ void cp_async16(uint32_t dst, const void* src) {
    asm volatile("cp.async.cg.shared.global [%0], [%1], 16;" :: "r"(dst), "l"(src));
}
__device__ __forceinline__ uint32_t smem_u32(const void* p) {
    uint32_t a;
    asm("{ .reg .u64 t; cvta.to.shared.u64 t, %1; cvt.u32.u64 %0, t; }" : "=r"(a) : "l"(p));
    return a;
}
#define CP_COMMIT() asm volatile("cp.async.commit_group;" ::: "memory")
#define CP_WAIT0()  asm volatile("cp.async.wait_group 0;" ::: "memory")
#define GRP_BAR(id) asm volatile("bar.sync %0, %1;" :: "r"(id), "r"(256) : "memory")

__device__ __forceinline__ uint32_t pack2(float lo, float hi) {
    __half2 h = __floats2half2_rn(lo, hi);
    return *reinterpret_cast<uint32_t*>(&h);
}
__device__ __forceinline__ float ex2(float x) {
    float y;
    asm("ex2.approx.f32 %0, %1;" : "=f"(y) : "f"(x));
    return y;
}
// ---- f16x2 epilogue helpers ----
__device__ __forceinline__ uint32_t cvt2h(float a, float b) {
    uint32_t d;
    asm("cvt.rn.f16x2.f32 %0, %1, %2;" : "=r"(d) : "f"(b), "f"(a));
    return d;
}
__device__ __forceinline__ uint32_t hfma2(uint32_t a, uint32_t b, uint32_t c) {
    uint32_t d;
    asm("fma.rn.f16x2 %0, %1, %2, %3;" : "=r"(d) : "r"(a), "r"(b), "r"(c));
    return d;
}
__device__ __forceinline__ uint32_t ex2h2(uint32_t a) {
    uint32_t d;
    asm("ex2.approx.f16x2 %0, %1;" : "=r"(d) : "r"(a));
    return d;
}
__device__ __forceinline__ uint32_t hadd2(uint32_t a, uint32_t b) {
    uint32_t d;
    asm("add.rn.f16x2 %0, %1, %2;" : "=r"(d) : "r"(a), "r"(b));
    return d;
}
__device__ __forceinline__ float hsum2(uint32_t v) {
    float lo, hi;
    asm("{ .reg .b16 l, h; mov.b32 {l, h}, %2; cvt.f32.f16 %0, l; cvt.f32.f16 %1, h; }"
        : "=f"(lo), "=f"(hi) : "r"(v));
    return lo + hi;
}

#define MMA(d, a, b0, b1) \
    asm volatile("mma.sync.aligned.m16n8k16.row.col.f32.f16.f16.f32 " \
                 "{%0,%1,%2,%3},{%4,%5,%6,%7},{%8,%9},{%0,%1,%2,%3};" \
                 : "+f"((d)[0]), "+f"((d)[1]), "+f"((d)[2]), "+f"((d)[3]) \
                 : "r"((a).x), "r"((a).y), "r"((a).z), "r"((a).w), "r"(b0), "r"(b1))
#define MMA_INIT(d, a, b0, b1) \
    asm volatile("mma.sync.aligned.m16n8k16.row.col.f32.f16.f16.f32 " \
                 "{%0,%1,%2,%3},{%4,%5,%6,%7},{%8,%9},{%10,%10,%10,%10};" \
                 : "=f"((d)[0]), "=f"((d)[1]), "=f"((d)[2]), "=f"((d)[3]) \
                 : "r"((a).x), "r"((a).y), "r"((a).z), "r"((a).w), "r"(b0), "r"(b1), "f"(0.f))

// ---------------------------------------------------------------------------
// Fused pre-pack: blocks [0,2048) pack A; blocks [2048,2176) pack B.
// ---------------------------------------------------------------------------
__global__ __launch_bounds__(256) void pack_ab_kernel(const float* __restrict__ x) {
    if (blockIdx.x < 2048) {
        int id = blockIdx.x * 256 + threadIdx.x;        // 0..524287
        int lane = id & 31, ks = (id >> 5) & 7, mt = (id >> 8) & 15, cta = id >> 12;
        int g = lane >> 2, t = lane & 3;
        int r0 = cta * BM + mt * 16 + g;
        int k0 = ks * 16 + t * 2;
        const float* p0 = x + (size_t)r0 * D_DIM;
        const float* p1 = p0 + 8 * D_DIM;
        float2 alo = *(const float2*)(p0 + k0);
        float2 blo = *(const float2*)(p1 + k0);
        float2 ahi = *(const float2*)(p0 + k0 + 8);
        float2 bhi = *(const float2*)(p1 + k0 + 8);
        uint4 o;
        o.x = pack2(alo.x, alo.y);
        o.y = pack2(blo.x, blo.y);
        o.z = pack2(ahi.x, ahi.y);
        o.w = pack2(bhi.x, bhi.y);
        gAh[id] = o;
    } else {
        int id = (blockIdx.x - 2048) * 256 + threadIdx.x;   // 0..32767
        int lane = id & 31, pp = (id >> 5) & 3, ks = (id >> 7) & 7, t = id >> 10;
        int g = lane >> 2, tt = lane & 3;
        int col0 = t * 64 + pp * 16 + g;
        int k0 = ks * 16 + tt * 2;
        const float* base0 = x + (size_t)col0 * M_UTT * D_DIM;
        const float* base1 = base0 + (size_t)8 * M_UTT * D_DIM;
        float2 s0l = {0.f, 0.f}, s0h = {0.f, 0.f}, s1l = {0.f, 0.f}, s1h = {0.f, 0.f};
#pragma unroll
        for (int m = 0; m < M_UTT; m++) {
            const float* r0 = base0 + m * D_DIM;
            const float* r1 = base1 + m * D_DIM;
            float2 v;
            v = *(const float2*)(r0 + k0);     s0l.x += v.x; s0l.y += v.y;
            v = *(const float2*)(r0 + k0 + 8); s0h.x += v.x; s0h.y += v.y;
            v = *(const float2*)(r1 + k0);     s1l.x += v.x; s1l.y += v.y;
            v = *(const float2*)(r1 + k0 + 8); s1h.x += v.x; s1h.y += v.y;
        }
        const float inv = 1.0f / M_UTT;
        uint4 o;
        o.x = pack2(s0l.x * inv, s0l.y * inv);
        o.y = pack2(s0h.x * inv, s0h.y * inv);
        o.z = pack2(s1l.x * inv, s1l.y * inv);
        o.w = pack2(s1h.x * inv, s1h.y * inv);
        gBh[id] = o;
    }
}

// ---------------------------------------------------------------------------
// group loader: n-group ng loads its 16 rows of stage t into its private buf
// ---------------------------------------------------------------------------
__device__ __forceinline__ void load_group_stage(uint32_t grpBase, int t, int ng, int gl) {
    const uint4* src = gBh + (size_t)t * STG_U4;
    uint32_t dst = grpBase + (t & 1) * GRP_BYTES;
#pragma unroll
    for (int j = 0; j < 2; j++) {
        int idx = gl + j * 256;             // 0..511
        int row_local = idx >> 5;           // 0..15
        int l = idx & 31;
        int s  = row_local >> 1;
        int jj = row_local & 1;
        int srow = s * 4 + 2 * ng + jj;     // row in the full 32-row stage
        cp_async16(dst + idx * 16, src + srow * 32 + l);
    }
}

// ---------------------------------------------------------------------------
// Main: fp16 mma.sync GEMM + log2-softmax. grid=128 single wave; 16 warps =
// 8(m) x 2(n). PIPELINE MAP: ng=(wid>>2)&1 so each SMSP holds warps of BOTH
// pipelines -> tensor-unit arbitration self-staggers MMA vs epilogue within
// the SMSP. A in registers; private B double buffers; f16x2 epilogue.
// ---------------------------------------------------------------------------
__global__ __launch_bounds__(THREADS, 1) void ge2e_main(const float* __restrict__ wp,
                                                        const float* __restrict__ bp,
                                                        float* __restrict__ out) {
    extern __shared__ uint4 dsm[];
    __shared__ float s_tgt[BM];
    __shared__ float s_red[BM][2];
    __shared__ float s_loss[BM];
    __shared__ bool  s_last;

    const int tid  = threadIdx.x;
    const int wid  = tid >> 5;
    const int lane = tid & 31;
    const int ng = (wid >> 2) & 1;                  // pipeline id, mixed per SMSP
    const int mg = (wid & 3) | ((wid >> 3) << 2);   // 0..7 unique within pipeline
    const int gl = mg * 32 + lane;                  // group-linear id 0..255
    const int g  = lane >> 2;
    const int t4 = lane & 3;

    const float L2E = 1.44269504088896341f;
    const float w2  = wp[0] * L2E;
    const float b2  = bp[0] * L2E;
    const float wd  = w2 * (16.0f / 15.0f);
    const float bd  = b2 - w2 * (1.0f / 15.0f);
    const uint32_t w2h = pack2(w2, w2);
    const uint32_t b2h = pack2(b2, b2);

    const uint32_t grpBase = smem_u32(dsm) + ng * (2 * GRP_BYTES);
    const int t_diag = blockIdx.x >> 2;

    load_group_stage(grpBase, 0, ng, gl);
    CP_COMMIT();

    // A -> registers (64 regs), reused for all 32 stages
    uint4 areg[2][8];
    {
        const uint4* gAs = gAh + (size_t)blockIdx.x * A_U4;
#pragma unroll
        for (int i = 0; i < 2; i++)
#pragma unroll
            for (int s = 0; s < 8; s++)
                areg[i][s] = gAs[((mg * 2 + i) * 8 + s) * 32 + lane];
    }

    float acc[2][4][4];
    float rsum[2][2] = {};
    int lrow[2], sp0[2], sp1[2];
#pragma unroll
    for (int mt = 0; mt < 2; mt++) {
        lrow[mt] = mg * 32 + mt * 16 + g;
        int gr = blockIdx.x * BM + lrow[mt];
        sp0[mt] = gr >> 4;
        sp1[mt] = (gr + 8) >> 4;
    }

    for (int t = 0; t < NSTAGE; t++) {
        CP_WAIT0();
        GRP_BAR(ng + 1);
        if (t + 1 < NSTAGE) {
            load_group_stage(grpBase, t + 1, ng, gl);
            CP_COMMIT();
        }

        const uint4* Bst = dsm + (ng * 2 + (t & 1)) * (GRP_BYTES / 16);

        // ---- MMA: 8 k-steps, A from registers, 2 LDS.128 per step ----
#pragma unroll
        for (int s = 0; s < 8; s++) {
            uint4 q0 = Bst[(s * 2 + 0) * 32 + lane];
            uint4 q1 = Bst[(s * 2 + 1) * 32 + lane];
            if (s == 0) {
                MMA_INIT(acc[0][0], areg[0][0], q0.x, q0.y); MMA_INIT(acc[0][1], areg[0][0], q0.z, q0.w);
                MMA_INIT(acc[1][0], areg[1][0], q0.x, q0.y); MMA_INIT(acc[1][1], areg[1][0], q0.z, q0.w);
                MMA_INIT(acc[0][2], areg[0][0], q1.x, q1.y); MMA_INIT(acc[0][3], areg[0][0], q1.z, q1.w);
                MMA_INIT(acc[1][2], areg[1][0], q1.x, q1.y); MMA_INIT(acc[1][3], areg[1][0], q1.z, q1.w);
            } else {
                MMA(acc[0][0], areg[0][s], q0.x, q0.y); MMA(acc[0][1], areg[0][s], q0.z, q0.w);
                MMA(acc[1][0], areg[1][s], q0.x, q0.y); MMA(acc[1][1], areg[1][s], q0.z, q0.w);
                MMA(acc[0][2], areg[0][s], q1.x, q1.y); MMA(acc[0][3], areg[0][s], q1.z, q1.w);
                MMA(acc[1][2], areg[1][s], q1.x, q1.y); MMA(acc[1][3], areg[1][s], q1.z, q1.w);
            }
        }

        // ---- epilogue (no barrier -> overlaps the other pipeline's MMAs) ----
        if (t == t_diag) {                  // exact fp32 path (1/32 stages)
#pragma unroll
            for (int mt = 0; mt < 2; mt++) {
#pragma unroll
                for (int nt = 0; nt < 4; nt++) {
                    const int col = t * 64 + ng * 32 + nt * 8 + t4 * 2;
                    float* A4 = acc[mt][nt];
                    float v, l;
                    v = A4[0]; l = fmaf(w2, v, b2);
                    if (col == sp0[mt])     { l = fmaf(wd, v, bd); s_tgt[lrow[mt]] = l; }
                    rsum[mt][0] += ex2(l);
                    v = A4[1]; l = fmaf(w2, v, b2);
                    if (col + 1 == sp0[mt]) { l = fmaf(wd, v, bd); s_tgt[lrow[mt]] = l; }
                    rsum[mt][0] += ex2(l);
                    v = A4[2]; l = fmaf(w2, v, b2);
                    if (col == sp1[mt])     { l = fmaf(wd, v, bd); s_tgt[lrow[mt] + 8] = l; }
                    rsum[mt][1] += ex2(l);
                    v = A4[3]; l = fmaf(w2, v, b2);
                    if (col + 1 == sp1[mt]) { l = fmaf(wd, v, bd); s_tgt[lrow[mt] + 8] = l; }
                    rsum[mt][1] += ex2(l);
                }
            }
        } else {                            // f16x2 fast path (31/32 stages)
#pragma unroll
            for (int mt = 0; mt < 2; mt++) {
                uint32_t h0 = 0u, h1 = 0u;   // f16x2 partials, rows g and g+8
#pragma unroll
                for (int nt = 0; nt < 4; nt++) {
                    float* A4 = acc[mt][nt];
                    h0 = hadd2(h0, ex2h2(hfma2(w2h, cvt2h(A4[0], A4[1]), b2h)));
                    h1 = hadd2(h1, ex2h2(hfma2(w2h, cvt2h(A4[2], A4[3]), b2h)));
                }
                rsum[mt][0] += hsum2(h0);
                rsum[mt][1] += hsum2(h1);
            }
        }
    }

    // reduce 4 t4-lanes per row, then the 2 n-groups
#pragma unroll
    for (int mt = 0; mt < 2; mt++)
#pragma unroll
        for (int hh = 0; hh < 2; hh++) {
            float v = rsum[mt][hh];
            v += __shfl_xor_sync(0xFFFFFFFFu, v, 1);
            v += __shfl_xor_sync(0xFFFFFFFFu, v, 2);
            if (t4 == 0) s_red[lrow[mt] + hh * 8][ng] = v;
        }
    __syncthreads();
    if (tid < BM) {
        float S = s_red[tid][0] + s_red[tid][1];
        s_loss[tid] = (log2f(S) - s_tgt[tid]) * 0.69314718055994531f;
    }
    __syncthreads();
    for (int o = 128; o > 0; o >>= 1) {
        if (tid < o) s_loss[tid] += s_loss[tid + o];
        __syncthreads();
    }
    if (tid == 0) {
        g_partial[blockIdx.x] = s_loss[0];
        __threadfence();
        unsigned old = atomicAdd(&g_ctr, 1u);
        s_last = (old == NCTA - 1);
    }
    __syncthreads();

    if (s_last) {
        if (tid == 0) g_ctr = 0;
        __threadfence();
        if (tid < NCTA) s_loss[tid] = g_partial[tid];
        __syncthreads();
        for (int o = NCTA / 2; o > 0; o >>= 1) {
            if (tid < o) s_loss[tid] += s_loss[tid + o];
            __syncthreads();
        }
        if (tid == 0) out[0] = s_loss[0] * (1.0f / (float)ROWS);
    }
}

extern "C" void kernel_launch(void* const* d_in, const int* in_sizes, int n_in,
                              void* d_out, int out_size) {
    const float* x = (const float*)d_in[0];
    const float* w = (const float*)d_in[1];
    const float* b = (const float*)d_in[2];
    float* out = (float*)d_out;

    cudaFuncSetAttribute(ge2e_main, cudaFuncAttributeMaxDynamicSharedMemorySize, DYN_SMEM);

    pack_ab_kernel<<<2048 + 128, 256>>>(x);
    ge2e_main<<<NCTA, THREADS, DYN_SMEM>>>(w, b, out);
}